// round 1
// baseline (speedup 1.0000x reference)
#include <cuda_runtime.h>

// Problem constants
#define N_B   128
#define N_W   64
#define L_W   32
#define T_D   108
#define P_D   19
#define F_D   128
#define M_D   128
#define NWALK 8192          // N_B * N_W
#define SCALE 0.08838834764831845f   // 1/sqrt(128)

// Scratch (device globals; no allocation allowed)
__device__ float g_emb[2 * NWALK * M_D];   // [sel][b][nw][c]  (8 MB)
__device__ float g_Wvl[F_D * M_D];         // Wv @ Wl folded
__device__ float g_bvl[M_D];               // 32*bv@Wl + bl

// ---------------------------------------------------------------------------
// Kernel 0: fold Wvl = Wv @ Wl ; bvl = 32*bv@Wl + bl
// ---------------------------------------------------------------------------
__global__ void prep_kernel(const float* __restrict__ Wv, const float* __restrict__ bv,
                            const float* __restrict__ Wl, const float* __restrict__ bl) {
    int c = threadIdx.x;
    if (blockIdx.x < 128) {
        int k = blockIdx.x;
        float acc = 0.f;
#pragma unroll 4
        for (int j = 0; j < 128; ++j) acc += Wv[k * 128 + j] * Wl[j * 128 + c];
        g_Wvl[k * 128 + c] = acc;
    } else {
        float acc = bl[c];
#pragma unroll 4
        for (int j = 0; j < 128; ++j) acc += 32.0f * bv[j] * Wl[j * 128 + c];
        g_bvl[c] = acc;
    }
}

// ---------------------------------------------------------------------------
// Kernel 1: per-walk attention. One block per walk (8192 blocks, 512 threads).
// Shared layout (floats):
//   xTp  [128][36]  transposed features (pos-selected; rows 19..127 common)
//   xTn  [19][36]   neg-selected position features only
//   qS   [2][32][128]  q rows (row-major)
//   kT   [2][128][33]  k transposed, stride 33 -> conflict-free lane reads
//   sc   [2][32][32]   softmax probs
//   scol [64], yv [256]
// ---------------------------------------------------------------------------
#define K1_XTP   0
#define K1_XTN   (128 * 36)                 // 4608
#define K1_QS    (K1_XTN + P_D * 36)        // 5292
#define K1_KT    (K1_QS + 2 * 32 * 128)     // 13484
#define K1_SC    (K1_KT + 2 * 128 * 33)     // 21932
#define K1_SCOL  (K1_SC + 2 * 32 * 32)      // 23980
#define K1_YV    (K1_SCOL + 64)             // 24044
#define K1_SMEM  ((K1_YV + 256) * 4)        // 97200 bytes

__global__ void __launch_bounds__(512, 2)
walk_kernel(const float* __restrict__ timef, const float* __restrict__ posf,
            const float* __restrict__ negf, const float* __restrict__ wgt,
            const int* __restrict__ sgn,
            const float* __restrict__ Wq, const float* __restrict__ bq,
            const float* __restrict__ Wk, const float* __restrict__ bk) {
    extern __shared__ float sm[];
    float* xTp  = sm + K1_XTP;
    float* xTn  = sm + K1_XTN;
    float* qS   = sm + K1_QS;
    float* kT   = sm + K1_KT;
    float* sc   = sm + K1_SC;
    float* scol = sm + K1_SCOL;
    float* yv   = sm + K1_YV;

    const int tid = threadIdx.x;
    const int w = blockIdx.x;
    const long tbase = (long)w * (L_W * T_D);
    const long pbase = (long)w * (L_W * P_D);
    const int  wbase = w * L_W;

    // -------- phase 0: load + transpose features --------
    for (int idx = tid; idx < L_W * T_D; idx += 512) {
        int r = idx / T_D, t = idx - r * T_D;
        xTp[(P_D + t) * 36 + r] = timef[tbase + idx];
    }
    if (tid < L_W) xTp[127 * 36 + tid] = wgt[wbase + tid];
    for (int idx = tid; idx < L_W * P_D; idx += 512) {
        int r = idx / P_D, p = idx - r * P_D;
        float vp = posf[pbase + idx];
        float vn = negf[pbase + idx];
        bool ps = (sgn[wbase + r] > 0);
        xTp[p * 36 + r] = ps ? vp : vn;
        xTn[p * 36 + r] = ps ? vn : vp;
    }
    __syncthreads();

    // -------- phase 1: Q,K projections (common + 19-dim pos/neg corrections) --------
    {
        const int c  = tid & 127;
        const int r0 = (tid >> 7) * 8;
#pragma unroll
        for (int mat = 0; mat < 2; ++mat) {
            const float* W  = mat ? Wk : Wq;
            const float* bb = mat ? bk : bq;
            float accC[8];
#pragma unroll
            for (int i = 0; i < 8; ++i) accC[i] = 0.f;
#pragma unroll 4
            for (int kk = P_D; kk < 128; ++kk) {
                float wv = W[kk * 128 + c];
                const float4 a0 = *(const float4*)&xTp[kk * 36 + r0];
                const float4 a1 = *(const float4*)&xTp[kk * 36 + r0 + 4];
                accC[0] += a0.x * wv; accC[1] += a0.y * wv;
                accC[2] += a0.z * wv; accC[3] += a0.w * wv;
                accC[4] += a1.x * wv; accC[5] += a1.y * wv;
                accC[6] += a1.z * wv; accC[7] += a1.w * wv;
            }
            float accP[8], accN[8];
#pragma unroll
            for (int i = 0; i < 8; ++i) { accP[i] = accC[i]; accN[i] = accC[i]; }
#pragma unroll 2
            for (int kk = 0; kk < P_D; ++kk) {
                float wv = W[kk * 128 + c];
                const float4 p0 = *(const float4*)&xTp[kk * 36 + r0];
                const float4 p1 = *(const float4*)&xTp[kk * 36 + r0 + 4];
                const float4 n0 = *(const float4*)&xTn[kk * 36 + r0];
                const float4 n1 = *(const float4*)&xTn[kk * 36 + r0 + 4];
                accP[0] += p0.x * wv; accP[1] += p0.y * wv;
                accP[2] += p0.z * wv; accP[3] += p0.w * wv;
                accP[4] += p1.x * wv; accP[5] += p1.y * wv;
                accP[6] += p1.z * wv; accP[7] += p1.w * wv;
                accN[0] += n0.x * wv; accN[1] += n0.y * wv;
                accN[2] += n0.z * wv; accN[3] += n0.w * wv;
                accN[4] += n1.x * wv; accN[5] += n1.y * wv;
                accN[6] += n1.z * wv; accN[7] += n1.w * wv;
            }
            float bias = bb[c];
            if (mat == 0) {
#pragma unroll
                for (int i = 0; i < 8; ++i) {
                    qS[(r0 + i) * 128 + c]        = accP[i] + bias;
                    qS[4096 + (r0 + i) * 128 + c] = accN[i] + bias;
                }
            } else {
#pragma unroll
                for (int i = 0; i < 8; ++i) {
                    kT[c * 33 + (r0 + i)]        = accP[i] + bias;
                    kT[4224 + c * 33 + (r0 + i)] = accN[i] + bias;
                }
            }
        }
    }
    __syncthreads();

    // -------- phase 2: scores + softmax (warp per 4 rows, same sel) --------
    {
        const int lane = tid & 31;
        const int wid  = tid >> 5;          // 0..15
        const int sel  = wid >> 3;          // warps 0-7 -> pos, 8-15 -> neg
        const int lb   = (wid & 7) * 4;     // 4 rows per warp
        const float* q0 = &qS[sel * 4096 + (lb + 0) * 128];
        const float* q1 = q0 + 128;
        const float* q2 = q0 + 256;
        const float* q3 = q0 + 384;
        const float* kb = &kT[sel * 4224 + lane];
        float a0 = 0.f, a1 = 0.f, a2 = 0.f, a3 = 0.f;
#pragma unroll 4
        for (int cc = 0; cc < 128; ++cc) {
            float kv = kb[cc * 33];
            a0 += q0[cc] * kv; a1 += q1[cc] * kv;
            a2 += q2[cc] * kv; a3 += q3[cc] * kv;
        }
        float av[4] = {a0 * SCALE, a1 * SCALE, a2 * SCALE, a3 * SCALE};
#pragma unroll
        for (int i = 0; i < 4; ++i) {
            float v = av[i];
            float mx = v;
#pragma unroll
            for (int off = 16; off; off >>= 1)
                mx = fmaxf(mx, __shfl_xor_sync(0xffffffffu, mx, off));
            float e = __expf(v - mx);
            float s = e;
#pragma unroll
            for (int off = 16; off; off >>= 1)
                s += __shfl_xor_sync(0xffffffffu, s, off);
            sc[sel * 1024 + (lb + i) * 32 + lane] = e / s;
        }
    }
    __syncthreads();

    // -------- phase 3: column sums of softmax --------
    if (tid < 64) {
        int sel = tid >> 5, m = tid & 31;
        float s = 0.f;
#pragma unroll 4
        for (int l = 0; l < 32; ++l) s += sc[sel * 1024 + l * 32 + m];
        scol[tid] = s;
    }
    __syncthreads();

    // -------- phase 4: y = s @ X --------
    if (tid < 256) {
        int sel = tid >> 7, k = tid & 127;
        const float* xb = (sel == 0 || k >= P_D) ? &xTp[k * 36] : &xTn[k * 36];
        const float* sp = &scol[sel * 32];
        float acc = 0.f;
#pragma unroll
        for (int m = 0; m < 32; ++m) acc += sp[m] * xb[m];
        yv[tid] = acc;
    }
    __syncthreads();

    // -------- phase 5: out = y @ Wvl + bvl  ->  g_emb --------
    if (tid < 256) {
        int sel = tid >> 7, cc = tid & 127;
        const float* yp = &yv[sel * 128];
        float acc = g_bvl[cc];
#pragma unroll 4
        for (int k = 0; k < 128; ++k) acc += yp[k] * g_Wvl[k * 128 + cc];
        g_emb[(sel * NWALK + w) * 128 + cc] = acc;
    }
}

// ---------------------------------------------------------------------------
// Kernel 2: path attention. One block per (sel, batch) -> 256 blocks, 512 thr.
// ---------------------------------------------------------------------------
#define K2_EMBT  0
#define K2_Q     (128 * 68)                 // 8704
#define K2_KT    (K2_Q + 64 * 128)          // 16896
#define K2_SC    (K2_KT + 128 * 65)         // 25216
#define K2_SCOL  (K2_SC + 64 * 64)          // 29312
#define K2_YV    (K2_SCOL + 64)             // 29376
#define K2_SMEM  ((K2_YV + 128) * 4)        // 118016 bytes

__global__ void __launch_bounds__(512, 1)
path_kernel(const float* __restrict__ Wqp, const float* __restrict__ bqp,
            const float* __restrict__ Wkp, const float* __restrict__ bkp,
            const float* __restrict__ Wvp, const float* __restrict__ bvp,
            float* __restrict__ out) {
    extern __shared__ float sm[];
    float* embT = sm + K2_EMBT;   // [128][68]  (k, m)
    float* q2   = sm + K2_Q;      // [64][128]
    float* kT2  = sm + K2_KT;     // [128][65]  (c, m)
    float* sc   = sm + K2_SC;     // [64][64]
    float* scol = sm + K2_SCOL;
    float* yv   = sm + K2_YV;

    const int tid = threadIdx.x;
    const int sel = blockIdx.x >> 7;
    const int b   = blockIdx.x & 127;
    const float* emb = &g_emb[(sel * N_B + b) * (N_W * M_D)];

    for (int idx = tid; idx < N_W * M_D; idx += 512) {
        int m = idx >> 7, k = idx & 127;
        embT[k * 68 + m] = emb[idx];
    }
    __syncthreads();

    // projections q,k : emb @ W + b
    {
        const int c  = tid & 127;
        const int r0 = (tid >> 7) * 16;
#pragma unroll
        for (int mat = 0; mat < 2; ++mat) {
            const float* W  = mat ? Wkp : Wqp;
            const float* bb = mat ? bkp : bqp;
            float acc[16];
#pragma unroll
            for (int i = 0; i < 16; ++i) acc[i] = 0.f;
#pragma unroll 2
            for (int kk = 0; kk < 128; ++kk) {
                float wv = W[kk * 128 + c];
                const float4 e0 = *(const float4*)&embT[kk * 68 + r0];
                const float4 e1 = *(const float4*)&embT[kk * 68 + r0 + 4];
                const float4 e2 = *(const float4*)&embT[kk * 68 + r0 + 8];
                const float4 e3 = *(const float4*)&embT[kk * 68 + r0 + 12];
                acc[0]  += e0.x * wv; acc[1]  += e0.y * wv; acc[2]  += e0.z * wv; acc[3]  += e0.w * wv;
                acc[4]  += e1.x * wv; acc[5]  += e1.y * wv; acc[6]  += e1.z * wv; acc[7]  += e1.w * wv;
                acc[8]  += e2.x * wv; acc[9]  += e2.y * wv; acc[10] += e2.z * wv; acc[11] += e2.w * wv;
                acc[12] += e3.x * wv; acc[13] += e3.y * wv; acc[14] += e3.z * wv; acc[15] += e3.w * wv;
            }
            float bias = bb[c];
            if (mat == 0) {
#pragma unroll
                for (int i = 0; i < 16; ++i) q2[(r0 + i) * 128 + c] = acc[i] + bias;
            } else {
#pragma unroll
                for (int i = 0; i < 16; ++i) kT2[c * 65 + (r0 + i)] = acc[i] + bias;
            }
        }
    }
    __syncthreads();

    // scores + softmax: warp per 4 rows; lane covers m and m+32
    {
        const int lane = tid & 31;
        const int wid  = tid >> 5;
        const int lb   = wid * 4;
        const float* q0 = &q2[(lb + 0) * 128];
        const float* q1 = q0 + 128;
        const float* q3 = q0 + 384;
        const float* qq2 = q0 + 256;
        const float* kbA = &kT2[lane];
        const float* kbB = &kT2[lane + 32];
        float aA[4] = {0.f, 0.f, 0.f, 0.f};
        float aB[4] = {0.f, 0.f, 0.f, 0.f};
#pragma unroll 4
        for (int cc = 0; cc < 128; ++cc) {
            float k0 = kbA[cc * 65];
            float k1 = kbB[cc * 65];
            float v0 = q0[cc], v1 = q1[cc], v2 = qq2[cc], v3 = q3[cc];
            aA[0] += v0 * k0; aB[0] += v0 * k1;
            aA[1] += v1 * k0; aB[1] += v1 * k1;
            aA[2] += v2 * k0; aB[2] += v2 * k1;
            aA[3] += v3 * k0; aB[3] += v3 * k1;
        }
#pragma unroll
        for (int i = 0; i < 4; ++i) {
            float x0 = aA[i] * SCALE, x1 = aB[i] * SCALE;
            float mx = fmaxf(x0, x1);
#pragma unroll
            for (int off = 16; off; off >>= 1)
                mx = fmaxf(mx, __shfl_xor_sync(0xffffffffu, mx, off));
            float e0 = __expf(x0 - mx), e1 = __expf(x1 - mx);
            float s = e0 + e1;
#pragma unroll
            for (int off = 16; off; off >>= 1)
                s += __shfl_xor_sync(0xffffffffu, s, off);
            float inv = 1.f / s;
            sc[(lb + i) * 64 + lane]      = e0 * inv;
            sc[(lb + i) * 64 + lane + 32] = e1 * inv;
        }
    }
    __syncthreads();

    if (tid < 64) {
        float s = 0.f;
#pragma unroll 4
        for (int l = 0; l < 64; ++l) s += sc[l * 64 + tid];
        scol[tid] = s;
    }
    __syncthreads();

    if (tid < 128) {
        float acc = 0.f;
#pragma unroll 4
        for (int m = 0; m < 64; ++m) acc += scol[m] * embT[tid * 68 + m];
        yv[tid] = acc;
    }
    __syncthreads();

    if (tid < 128) {
        float acc = 64.0f * bvp[tid];
#pragma unroll 4
        for (int k = 0; k < 128; ++k) acc += yv[k] * Wvp[k * 128 + tid];
        out[sel * (N_B * M_D) + b * 128 + tid] = acc;
    }
}

// ---------------------------------------------------------------------------
extern "C" void kernel_launch(void* const* d_in, const int* in_sizes, int n_in,
                              void* d_out, int out_size) {
    const float* timef = (const float*)d_in[0];
    const float* posf  = (const float*)d_in[1];
    const float* negf  = (const float*)d_in[2];
    const float* wgt   = (const float*)d_in[3];
    const int*   sgn   = (const int*)  d_in[4];
    const float* Wq    = (const float*)d_in[5];
    const float* bq    = (const float*)d_in[6];
    const float* Wk    = (const float*)d_in[7];
    const float* bk    = (const float*)d_in[8];
    const float* Wv    = (const float*)d_in[9];
    const float* bv    = (const float*)d_in[10];
    const float* Wl    = (const float*)d_in[11];
    const float* bl    = (const float*)d_in[12];
    const float* Wqp   = (const float*)d_in[13];
    const float* bqp   = (const float*)d_in[14];
    const float* Wkp   = (const float*)d_in[15];
    const float* bkp   = (const float*)d_in[16];
    const float* Wvp   = (const float*)d_in[17];
    const float* bvp   = (const float*)d_in[18];

    cudaFuncSetAttribute(walk_kernel, cudaFuncAttributeMaxDynamicSharedMemorySize, K1_SMEM);
    cudaFuncSetAttribute(path_kernel, cudaFuncAttributeMaxDynamicSharedMemorySize, K2_SMEM);

    prep_kernel<<<129, 128>>>(Wv, bv, Wl, bl);
    walk_kernel<<<NWALK, 512, K1_SMEM>>>(timef, posf, negf, wgt, sgn, Wq, bq, Wk, bk);
    path_kernel<<<256, 512, K2_SMEM>>>(Wqp, bqp, Wkp, bkp, Wvp, bvp, (float*)d_out);
}